// round 8
// baseline (speedup 1.0000x reference)
#include <cuda_runtime.h>

// Problem constants (fixed by setup_inputs)
#define BS      64
#define C_TS    128
#define C_CTS   256
#define T_LEN   2048
#define N_CAT   32
#define N_CONT  64

#define MASK_P    0.15f
#define REPLACE_P 0.80f
#define RAND_HI   0.90f   // REPLACE_P + RANDOM_P

// Scratch (static device allocations)
__device__ unsigned char g_mult_ts [BS * T_LEN];   // 0 = zero-out, 1 = keep
__device__ unsigned char g_mult_cts[BS * T_LEN];
__device__ unsigned g_swap_ts [BS * T_LEN];        // packed (b<<22)|(t<<11)|r
__device__ unsigned g_swap_cts[BS * T_LEN];
__device__ unsigned g_nswap[2];                    // [0]=ts, [1]=cts

// ---------------------------------------------------------------------------
__global__ void reset_kernel()
{
    g_nswap[0] = 0;
    g_nswap[1] = 0;
}

// ---------------------------------------------------------------------------
// Precompute: multiplier bytes + compacted swap list. Thread handles 4 t.
// Tail block handles static cat/cont outputs.
// ---------------------------------------------------------------------------
#define DEC_N        (BS * T_LEN)                       // 131072 per tensor
#define DEC_THREADS  256
#define DEC_PER_T    4
#define DEC_BLOCKS   ((2 * DEC_N) / (DEC_THREADS * DEC_PER_T))   // 256

__global__ void __launch_bounds__(DEC_THREADS)
precompute_kernel(const float* __restrict__ u_ts_mask,
                  const float* __restrict__ u_ts_act,
                  const int*   __restrict__ r_ts_idx,
                  const float* __restrict__ u_cts_mask,
                  const float* __restrict__ u_cts_act,
                  const int*   __restrict__ r_cts_idx,
                  const int*   __restrict__ x_cat,
                  const float* __restrict__ x_cont,
                  const float* __restrict__ u_cat_mask,
                  const float* __restrict__ u_cat_act,
                  const int*   __restrict__ r_cat_val,
                  const float* __restrict__ u_cont_mask,
                  const float* __restrict__ u_cont_act,
                  const int*   __restrict__ r_cont_idx,
                  float* __restrict__ out_cat,
                  float* __restrict__ out_cont)
{
    unsigned blk = blockIdx.x;
    unsigned tid = threadIdx.x;

    if (blk < DEC_BLOCKS) {
        unsigned base = (blk * DEC_THREADS + tid) * DEC_PER_T;
        const float* um;
        const float* ua;
        const int*   ri;
        unsigned char* mult;
        unsigned* list;
        unsigned* cnt;
        unsigned off;
        if (base < DEC_N) {
            um = u_ts_mask;  ua = u_ts_act;  ri = r_ts_idx;
            mult = g_mult_ts;  list = g_swap_ts;  cnt = &g_nswap[0];
            off = base;
        } else {
            um = u_cts_mask; ua = u_cts_act; ri = r_cts_idx;
            mult = g_mult_cts; list = g_swap_cts; cnt = &g_nswap[1];
            off = base - DEC_N;
        }

        float4 m4 = *(const float4*)(um + off);
        float4 a4 = *(const float4*)(ua + off);
        int4   r4 = *(const int4*)  (ri + off);

        float umv[4] = {m4.x, m4.y, m4.z, m4.w};
        float uav[4] = {a4.x, a4.y, a4.z, a4.w};
        int   rv [4] = {r4.x, r4.y, r4.z, r4.w};

        unsigned b = off >> 11;              // / T_LEN
        unsigned t_base = off & (T_LEN - 1);

        unsigned char mb[4];
        unsigned swaps[4];
        int nswaps = 0;
#pragma unroll
        for (int i = 0; i < 4; i++) {
            bool masked = umv[i] < MASK_P;
            bool rep = masked && (uav[i] < REPLACE_P);
            bool rnd = masked && (uav[i] >= REPLACE_P) && (uav[i] < RAND_HI);
            mb[i] = rep ? 0 : 1;
            if (rnd) {
                swaps[nswaps++] = (b << 22) | ((t_base + i) << 11) | (unsigned)rv[i];
            }
        }

        uchar4 pk = make_uchar4(mb[0], mb[1], mb[2], mb[3]);
        *(uchar4*)(mult + off) = pk;

        if (nswaps > 0) {
            unsigned slot = atomicAdd(cnt, (unsigned)nswaps);
            for (int i = 0; i < nswaps; i++) list[slot + i] = swaps[i];
        }
        return;
    }

    // ---- static cat + cont (single tail block, 256 threads) ----
    __shared__ float partial[4][N_CONT];
    __shared__ float means[N_CONT];

    {
        unsigned j = tid & (N_CONT - 1);
        unsigned chunk = tid >> 6;
        float s = 0.0f;
        for (unsigned b = chunk * 16; b < chunk * 16 + 16; b++)
            s += x_cont[b * N_CONT + j];
        partial[chunk][j] = s;
    }
    __syncthreads();
    if (tid < N_CONT) {
        means[tid] = (partial[0][tid] + partial[1][tid] +
                      partial[2][tid] + partial[3][tid]) * (1.0f / BS);
    }
    __syncthreads();

    for (unsigned i = tid; i < BS * N_CAT; i += DEC_THREADS) {
        float um = u_cat_mask[i];
        float ua = u_cat_act[i];
        int v = x_cat[i];
        if (um < MASK_P) {
            if (ua < REPLACE_P)    v = 0;
            else if (ua < RAND_HI) v = r_cat_val[i];
        }
        out_cat[i] = (float)v;
    }

    for (unsigned i = tid; i < BS * N_CONT; i += DEC_THREADS) {
        unsigned j = i & (N_CONT - 1);
        float um = u_cont_mask[i];
        float ua = u_cont_act[i];
        float v = x_cont[i];
        if (um < MASK_P) {
            if (ua < REPLACE_P)    v = means[j];
            else if (ua < RAND_HI) v = x_cont[r_cont_idx[i] * N_CONT + j];
        }
        out_cont[i] = v;
    }
}

// ---------------------------------------------------------------------------
// Main streaming kernel: pure branchless select. Thread = 4 consecutive t.
// Loads: uchar4 mult (L2-pinned, 128KB/tensor) + float4 x. Store: float4.
// No branches, no gathers, no divergence.
// ---------------------------------------------------------------------------
#define MAIN_THREADS 256
#define GROUPS_PER_ROW (T_LEN / 4)                                        // 512
#define TS_BLOCKS    ((int)((long)BS * C_TS  * T_LEN / 4 / MAIN_THREADS)) // 16384
#define CTS_BLOCKS   ((int)((long)BS * C_CTS * T_LEN / 4 / MAIN_THREADS)) // 32768

__global__ void __launch_bounds__(MAIN_THREADS)
stream_kernel(const float* __restrict__ x_ts,
              float* __restrict__ out_ts,
              const float* __restrict__ x_cts,
              float* __restrict__ out_cts)
{
    unsigned blk = blockIdx.x;
    const float* x;
    float* out;
    const unsigned char* mult;
    unsigned logC;
    if (blk < TS_BLOCKS) {
        x = x_ts; out = out_ts; mult = g_mult_ts; logC = 7;
    } else {
        blk -= TS_BLOCKS;
        x = x_cts; out = out_cts; mult = g_mult_cts; logC = 8;
    }

    unsigned gid = blk * MAIN_THREADS + threadIdx.x;
    unsigned t0 = (gid & (GROUPS_PER_ROW - 1)) * 4;
    unsigned bc = gid >> 9;
    unsigned b  = bc >> logC;

    uchar4 m4 = *(const uchar4*)(mult + b * T_LEN + t0);
    float4 x4 = *(const float4*)(x + bc * T_LEN + t0);

    float4 o4;
    o4.x = m4.x ? x4.x : 0.0f;
    o4.y = m4.y ? x4.y : 0.0f;
    o4.z = m4.z ? x4.z : 0.0f;
    o4.w = m4.w ? x4.w : 0.0f;

    *(float4*)(out + bc * T_LEN + t0) = o4;
}

// ---------------------------------------------------------------------------
// Fixup kernel: apply swaps. element idx -> (swap s, channel c).
// out[b, c, t] = x[b, c, r]. Grid-stride; counts read from device.
// ---------------------------------------------------------------------------
#define FIX_BLOCKS   512
#define FIX_THREADS  256

__global__ void __launch_bounds__(FIX_THREADS)
fixup_kernel(const float* __restrict__ x_ts,
             float* __restrict__ out_ts,
             const float* __restrict__ x_cts,
             float* __restrict__ out_cts)
{
    unsigned n_ts  = g_nswap[0];
    unsigned n_cts = g_nswap[1];
    unsigned total_ts  = n_ts  * C_TS;
    unsigned total     = total_ts + n_cts * C_CTS;

    for (unsigned idx = blockIdx.x * FIX_THREADS + threadIdx.x;
         idx < total;
         idx += gridDim.x * FIX_THREADS) {
        unsigned e;
        const float* x;
        float* out;
        unsigned s, c, logT;
        if (idx < total_ts) {
            s = idx >> 7;  c = idx & (C_TS - 1);
            e = g_swap_ts[s];  x = x_ts;  out = out_ts;  logT = 7;
        } else {
            unsigned j = idx - total_ts;
            s = j >> 8;  c = j & (C_CTS - 1);
            e = g_swap_cts[s]; x = x_cts; out = out_cts; logT = 8;
        }
        unsigned b = e >> 22;
        unsigned t = (e >> 11) & 0x7FF;
        unsigned r = e & 0x7FF;
        unsigned bc = (b << logT) + c;       // b*C + c
        out[(unsigned long)bc * T_LEN + t] = x[(unsigned long)bc * T_LEN + r];
    }
}

// ---------------------------------------------------------------------------
// Launch
// ---------------------------------------------------------------------------
extern "C" void kernel_launch(void* const* d_in, const int* in_sizes, int n_in,
                              void* d_out, int out_size)
{
    const float* x_ts     = (const float*)d_in[0];
    const float* x_ts_cat = (const float*)d_in[1];
    const int*   x_cat    = (const int*)  d_in[2];
    const float* x_cont   = (const float*)d_in[3];

    const float* u_ts_mask  = (const float*)d_in[4];
    const float* u_ts_act   = (const float*)d_in[5];
    const int*   r_ts_idx   = (const int*)  d_in[6];
    const float* u_cts_mask = (const float*)d_in[7];
    const float* u_cts_act  = (const float*)d_in[8];
    const int*   r_cts_idx  = (const int*)  d_in[9];

    const float* u_cat_mask = (const float*)d_in[10];
    const float* u_cat_act  = (const float*)d_in[11];
    const int*   r_cat_val  = (const int*)  d_in[12];
    const float* u_cont_mask= (const float*)d_in[13];
    const float* u_cont_act = (const float*)d_in[14];
    const int*   r_cont_idx = (const int*)  d_in[15];

    float* out = (float*)d_out;
    const long TS_ELEMS  = (long)BS * C_TS  * T_LEN;   // 16,777,216
    const long CTS_ELEMS = (long)BS * C_CTS * T_LEN;   // 33,554,432
    float* out_ts   = out;
    float* out_cts  = out + TS_ELEMS;
    float* out_cat  = out + TS_ELEMS + CTS_ELEMS;
    float* out_cont = out_cat + (long)BS * N_CAT;

    reset_kernel<<<1, 1>>>();

    precompute_kernel<<<DEC_BLOCKS + 1, DEC_THREADS>>>(
        u_ts_mask, u_ts_act, r_ts_idx,
        u_cts_mask, u_cts_act, r_cts_idx,
        x_cat, x_cont,
        u_cat_mask, u_cat_act, r_cat_val,
        u_cont_mask, u_cont_act, r_cont_idx,
        out_cat, out_cont);

    stream_kernel<<<TS_BLOCKS + CTS_BLOCKS, MAIN_THREADS>>>(
        x_ts, out_ts, x_ts_cat, out_cts);

    fixup_kernel<<<FIX_BLOCKS, FIX_THREADS>>>(
        x_ts, out_ts, x_ts_cat, out_cts);
}

// round 9
// speedup vs baseline: 1.2350x; 1.2350x over previous
#include <cuda_runtime.h>

// Problem constants (fixed by setup_inputs)
#define BS      64
#define C_TS    128
#define C_CTS   256
#define T_LEN   2048
#define N_CAT   32
#define N_CONT  64

#define MASK_P    0.15f
#define REPLACE_P 0.80f
#define RAND_HI   0.90f   // REPLACE_P + RANDOM_P

// ---------------------------------------------------------------------------
// Single fused kernel. Blocks [0, TS_BLOCKS): x_ts. [TS_BLOCKS, +CTS_BLOCKS):
// x_ts_cat. Last block: static cat/cont.
// Thread = 4 consecutive t. Decisions computed inline from u_mask/u_act/r_idx
// (per-(b,t) arrays, 512KB each — L2-resident after first channel touch).
// ---------------------------------------------------------------------------
#define MAIN_THREADS 256
#define GROUPS_PER_ROW (T_LEN / 4)                                        // 512
#define TS_BLOCKS    ((int)((long)BS * C_TS  * T_LEN / 4 / MAIN_THREADS)) // 16384
#define CTS_BLOCKS   ((int)((long)BS * C_CTS * T_LEN / 4 / MAIN_THREADS)) // 32768

__global__ void __launch_bounds__(MAIN_THREADS)
fused_kernel(const float* __restrict__ x_ts,
             float* __restrict__ out_ts,
             const float* __restrict__ x_cts,
             float* __restrict__ out_cts,
             const float* __restrict__ u_ts_mask,
             const float* __restrict__ u_ts_act,
             const int*   __restrict__ r_ts_idx,
             const float* __restrict__ u_cts_mask,
             const float* __restrict__ u_cts_act,
             const int*   __restrict__ r_cts_idx,
             const int*   __restrict__ x_cat,
             const float* __restrict__ x_cont,
             const float* __restrict__ u_cat_mask,
             const float* __restrict__ u_cat_act,
             const int*   __restrict__ r_cat_val,
             const float* __restrict__ u_cont_mask,
             const float* __restrict__ u_cont_act,
             const int*   __restrict__ r_cont_idx,
             float* __restrict__ out_cat,
             float* __restrict__ out_cont)
{
    unsigned blk = blockIdx.x;
    unsigned tid = threadIdx.x;

    if (blk < TS_BLOCKS + CTS_BLOCKS) {
        const float* x;
        float* out;
        const float* u_mask;
        const float* u_act;
        const int*   r_idx;
        unsigned logC;
        if (blk < TS_BLOCKS) {
            x = x_ts; out = out_ts;
            u_mask = u_ts_mask; u_act = u_ts_act; r_idx = r_ts_idx;
            logC = 7;
        } else {
            blk -= TS_BLOCKS;
            x = x_cts; out = out_cts;
            u_mask = u_cts_mask; u_act = u_cts_act; r_idx = r_cts_idx;
            logC = 8;
        }

        unsigned gid = blk * MAIN_THREADS + tid;
        unsigned t0 = (gid & (GROUPS_PER_ROW - 1)) * 4;
        unsigned bc = gid >> 9;                 // / GROUPS_PER_ROW
        unsigned b  = bc >> logC;
        unsigned brow = b * T_LEN + t0;

        // decision loads (L2-resident after first channel) + x load
        const float4 um4 = *(const float4*)(u_mask + brow);
        const float4 ua4 = *(const float4*)(u_act  + brow);
        const int4   r4  = *(const int4*)  (r_idx  + brow);

        const float* row = x + (unsigned long)bc * T_LEN;
        float4 x4 = *(const float4*)(row + t0);

        float xv[4] = {x4.x, x4.y, x4.z, x4.w};
        float um[4] = {um4.x, um4.y, um4.z, um4.w};
        float ua[4] = {ua4.x, ua4.y, ua4.z, ua4.w};
        int   rv[4] = {r4.x, r4.y, r4.z, r4.w};

        float o[4];
#pragma unroll
        for (int i = 0; i < 4; i++) {
            float v = xv[i];
            if (um[i] < MASK_P) {
                if (ua[i] < REPLACE_P)      v = 0.0f;
                else if (ua[i] < RAND_HI)   v = __ldg(row + rv[i]);
            }
            o[i] = v;
        }

        *(float4*)(out + (unsigned long)bc * T_LEN + t0) =
            make_float4(o[0], o[1], o[2], o[3]);
        return;
    }

    // ---- static cat + cont (single tail block, 256 threads) ----
    __shared__ float partial[4][N_CONT];
    __shared__ float means[N_CONT];

    {
        unsigned j = tid & (N_CONT - 1);     // column
        unsigned chunk = tid >> 6;           // 0..3, 16 rows each
        float s = 0.0f;
        for (unsigned b = chunk * 16; b < chunk * 16 + 16; b++)
            s += x_cont[b * N_CONT + j];
        partial[chunk][j] = s;
    }
    __syncthreads();
    if (tid < N_CONT) {
        means[tid] = (partial[0][tid] + partial[1][tid] +
                      partial[2][tid] + partial[3][tid]) * (1.0f / BS);
    }
    __syncthreads();

    // categorical: BS*N_CAT = 2048 elements
    for (unsigned i = tid; i < BS * N_CAT; i += MAIN_THREADS) {
        float um = u_cat_mask[i];
        float ua = u_cat_act[i];
        int v = x_cat[i];
        if (um < MASK_P) {
            if (ua < REPLACE_P)    v = 0;
            else if (ua < RAND_HI) v = r_cat_val[i];
        }
        out_cat[i] = (float)v;
    }

    // continuous: BS*N_CONT = 4096 elements
    for (unsigned i = tid; i < BS * N_CONT; i += MAIN_THREADS) {
        unsigned j = i & (N_CONT - 1);
        float um = u_cont_mask[i];
        float ua = u_cont_act[i];
        float v = x_cont[i];
        if (um < MASK_P) {
            if (ua < REPLACE_P)    v = means[j];
            else if (ua < RAND_HI) v = x_cont[r_cont_idx[i] * N_CONT + j];
        }
        out_cont[i] = v;
    }
}

// ---------------------------------------------------------------------------
// Launch: single kernel.
// ---------------------------------------------------------------------------
extern "C" void kernel_launch(void* const* d_in, const int* in_sizes, int n_in,
                              void* d_out, int out_size)
{
    const float* x_ts     = (const float*)d_in[0];
    const float* x_ts_cat = (const float*)d_in[1];
    const int*   x_cat    = (const int*)  d_in[2];
    const float* x_cont   = (const float*)d_in[3];

    const float* u_ts_mask  = (const float*)d_in[4];
    const float* u_ts_act   = (const float*)d_in[5];
    const int*   r_ts_idx   = (const int*)  d_in[6];
    const float* u_cts_mask = (const float*)d_in[7];
    const float* u_cts_act  = (const float*)d_in[8];
    const int*   r_cts_idx  = (const int*)  d_in[9];

    const float* u_cat_mask = (const float*)d_in[10];
    const float* u_cat_act  = (const float*)d_in[11];
    const int*   r_cat_val  = (const int*)  d_in[12];
    const float* u_cont_mask= (const float*)d_in[13];
    const float* u_cont_act = (const float*)d_in[14];
    const int*   r_cont_idx = (const int*)  d_in[15];

    float* out = (float*)d_out;
    const long TS_ELEMS  = (long)BS * C_TS  * T_LEN;   // 16,777,216
    const long CTS_ELEMS = (long)BS * C_CTS * T_LEN;   // 33,554,432
    float* out_ts   = out;
    float* out_cts  = out + TS_ELEMS;
    float* out_cat  = out + TS_ELEMS + CTS_ELEMS;
    float* out_cont = out_cat + (long)BS * N_CAT;

    fused_kernel<<<TS_BLOCKS + CTS_BLOCKS + 1, MAIN_THREADS>>>(
        x_ts, out_ts, x_ts_cat, out_cts,
        u_ts_mask, u_ts_act, r_ts_idx,
        u_cts_mask, u_cts_act, r_cts_idx,
        x_cat, x_cont,
        u_cat_mask, u_cat_act, r_cat_val,
        u_cont_mask, u_cont_act, r_cont_idx,
        out_cat, out_cont);
}